// round 1
// baseline (speedup 1.0000x reference)
#include <cuda_runtime.h>
#include <cstdint>

#define BB 16
#define NN 2048
#define DG 512
#define DH 512
#define OUTD 512
#define KTOP 512

// scratch (no cudaMalloc allowed)
__device__ float g_e1[BB * NN * OUTD];
__device__ float g_e2[BB * NN * OUTD];
__device__ float g_hb1[BB * OUTD];
__device__ float g_hb2[BB * OUTD];
__device__ unsigned int g_minbits[BB];
__device__ float g_dinv[BB * NN];

__device__ __forceinline__ unsigned int fmap(float f) {
    unsigned int u = __float_as_uint(f);
    return (u & 0x80000000u) ? ~u : (u | 0x80000000u);
}
__device__ __forceinline__ float funmap(unsigned int m) {
    unsigned int u = (m & 0x80000000u) ? (m ^ 0x80000000u) : ~m;
    return __uint_as_float(u);
}

__global__ void k_init() {
    if (threadIdx.x < BB) g_minbits[threadIdx.x] = 0xFFFFFFFFu;
}

// per-batch hidden contribution: g_hb[b,o] = sum_d h[b,d] * W[512+d, o]
__global__ void k_hb(const float* __restrict__ hidden,
                     const float* __restrict__ W1,
                     const float* __restrict__ W2) {
    int b = blockIdx.x;
    int o = threadIdx.x;  // 512 threads
    const float* h = hidden + b * DH;
    float a1 = 0.f, a2 = 0.f;
#pragma unroll 4
    for (int d = 0; d < DH; d++) {
        float hv = h[d];
        a1 = fmaf(hv, W1[(size_t)(DG + d) * OUTD + o], a1);
        a2 = fmaf(hv, W2[(size_t)(DG + d) * OUTD + o], a2);
    }
    g_hb1[b * OUTD + o] = a1;
    g_hb2[b * OUTD + o] = a2;
}

#define BM 128
#define BN 128
#define BK 16

// e1/e2 GEMM: C[32768, 1024] = ge[32768,512] @ W[512,1024] (+ hb, bias, mask)
__global__ __launch_bounds__(256) void k_gemm1(
    const float* __restrict__ ge, const float* __restrict__ mask,
    const float* __restrict__ W1, const float* __restrict__ b1,
    const float* __restrict__ W2, const float* __restrict__ b2) {
    __shared__ float As[BK][BM];
    __shared__ float Bs[BK][BN];
    int bn = blockIdx.x, bm = blockIdx.y;
    int tid = threadIdx.x;
    int tx = tid % 16, ty = tid / 16;
    int row0 = bm * BM, col0 = bn * BN;

    int a_row = tid / 4;
    int a_k4 = (tid % 4) * 4;
    int b_k = tid / 32;
    int b_n4 = (tid % 32) * 4;

    float acc[8][8];
#pragma unroll
    for (int i = 0; i < 8; i++)
#pragma unroll
        for (int j = 0; j < 8; j++) acc[i][j] = 0.f;

    for (int k0 = 0; k0 < DG; k0 += BK) {
#pragma unroll
        for (int r = 0; r < 2; r++) {
            int row = a_row + r * 64;
            float4 v = *(const float4*)(ge + (size_t)(row0 + row) * DG + k0 + a_k4);
            As[a_k4 + 0][row] = v.x;
            As[a_k4 + 1][row] = v.y;
            As[a_k4 + 2][row] = v.z;
            As[a_k4 + 3][row] = v.w;
        }
#pragma unroll
        for (int r = 0; r < 2; r++) {
            int kk = b_k + r * 8;
            int col = col0 + b_n4;
            const float* Wp = (col < OUTD) ? (W1 + (size_t)(k0 + kk) * OUTD + col)
                                           : (W2 + (size_t)(k0 + kk) * OUTD + (col - OUTD));
            *(float4*)&Bs[kk][b_n4] = *(const float4*)Wp;
        }
        __syncthreads();
#pragma unroll
        for (int kk = 0; kk < BK; kk++) {
            float4 a0 = *(const float4*)&As[kk][ty * 8];
            float4 a1v = *(const float4*)&As[kk][ty * 8 + 4];
            float4 bv0 = *(const float4*)&Bs[kk][tx * 8];
            float4 bv1 = *(const float4*)&Bs[kk][tx * 8 + 4];
            float av[8] = {a0.x, a0.y, a0.z, a0.w, a1v.x, a1v.y, a1v.z, a1v.w};
            float bv[8] = {bv0.x, bv0.y, bv0.z, bv0.w, bv1.x, bv1.y, bv1.z, bv1.w};
#pragma unroll
            for (int i = 0; i < 8; i++)
#pragma unroll
                for (int j = 0; j < 8; j++) acc[i][j] = fmaf(av[i], bv[j], acc[i][j]);
        }
        __syncthreads();
    }

#pragma unroll
    for (int i = 0; i < 8; i++) {
        int m = row0 + ty * 8 + i;
        int b = m >> 11;
        float mk = mask[m];
#pragma unroll
        for (int j = 0; j < 8; j++) {
            int n = col0 + tx * 8 + j;
            if (n < OUTD) {
                g_e1[(size_t)m * OUTD + n] = mk * (acc[i][j] + g_hb1[b * OUTD + n]) + b1[n];
            } else {
                int n2 = n - OUTD;
                g_e2[(size_t)m * OUTD + n2] = mk * (acc[i][j] + g_hb2[b * OUTD + n2]) + b2[n2];
            }
        }
    }
}

// batched Adj = e1 @ e2^T, raw values to out; fused per-batch min (atomicMin on mapped bits)
__global__ __launch_bounds__(256) void k_gemm2(float* __restrict__ out) {
    __shared__ float As[BK][BM];
    __shared__ float Bs[BK][BN];
    __shared__ unsigned int sMin;
    int b = blockIdx.z;
    int bn = blockIdx.x, bm = blockIdx.y;
    int tid = threadIdx.x;
    int tx = tid % 16, ty = tid / 16;
    int row0 = bm * BM, col0 = bn * BN;
    const float* e1p = g_e1 + (size_t)b * NN * OUTD;
    const float* e2p = g_e2 + (size_t)b * NN * OUTD;

    int a_row = tid / 4;
    int a_k4 = (tid % 4) * 4;

    if (tid == 0) sMin = 0xFFFFFFFFu;

    float acc[8][8];
#pragma unroll
    for (int i = 0; i < 8; i++)
#pragma unroll
        for (int j = 0; j < 8; j++) acc[i][j] = 0.f;

    for (int k0 = 0; k0 < OUTD; k0 += BK) {
#pragma unroll
        for (int r = 0; r < 2; r++) {
            int row = a_row + r * 64;
            float4 v = *(const float4*)(e1p + (size_t)(row0 + row) * OUTD + k0 + a_k4);
            As[a_k4 + 0][row] = v.x;
            As[a_k4 + 1][row] = v.y;
            As[a_k4 + 2][row] = v.z;
            As[a_k4 + 3][row] = v.w;
            float4 w = *(const float4*)(e2p + (size_t)(col0 + row) * OUTD + k0 + a_k4);
            Bs[a_k4 + 0][row] = w.x;
            Bs[a_k4 + 1][row] = w.y;
            Bs[a_k4 + 2][row] = w.z;
            Bs[a_k4 + 3][row] = w.w;
        }
        __syncthreads();
#pragma unroll
        for (int kk = 0; kk < BK; kk++) {
            float4 a0 = *(const float4*)&As[kk][ty * 8];
            float4 a1v = *(const float4*)&As[kk][ty * 8 + 4];
            float4 bv0 = *(const float4*)&Bs[kk][tx * 8];
            float4 bv1 = *(const float4*)&Bs[kk][tx * 8 + 4];
            float av[8] = {a0.x, a0.y, a0.z, a0.w, a1v.x, a1v.y, a1v.z, a1v.w};
            float bv[8] = {bv0.x, bv0.y, bv0.z, bv0.w, bv1.x, bv1.y, bv1.z, bv1.w};
#pragma unroll
            for (int i = 0; i < 8; i++)
#pragma unroll
                for (int j = 0; j < 8; j++) acc[i][j] = fmaf(av[i], bv[j], acc[i][j]);
        }
        __syncthreads();
    }

    float lmin = 3.402823466e+38f;
    float* outb = out + (size_t)b * NN * NN;
#pragma unroll
    for (int i = 0; i < 8; i++) {
        int m = row0 + ty * 8 + i;
        float* op = outb + (size_t)m * NN + col0 + tx * 8;
        float4 v0 = make_float4(acc[i][0], acc[i][1], acc[i][2], acc[i][3]);
        float4 v1 = make_float4(acc[i][4], acc[i][5], acc[i][6], acc[i][7]);
        *(float4*)op = v0;
        *(float4*)(op + 4) = v1;
#pragma unroll
        for (int j = 0; j < 8; j++) lmin = fminf(lmin, acc[i][j]);
    }
#pragma unroll
    for (int off = 16; off > 0; off >>= 1)
        lmin = fminf(lmin, __shfl_xor_sync(0xFFFFFFFFu, lmin, off));
    if ((tid & 31) == 0) atomicMin(&sMin, fmap(lmin));
    __syncthreads();
    if (tid == 0) atomicMin(&g_minbits[b], sMin);
}

// per-row: min-shift, mask, exact top-k(512) with jax tie semantics, rowsum, scale by d_i
#define RT 256
#define EPT (NN / RT)  // 8
__global__ __launch_bounds__(RT) void k_row(float* __restrict__ out,
                                            const float* __restrict__ mask) {
    __shared__ float vals[NN];
    __shared__ unsigned int keys[NN];
    __shared__ unsigned int hist[256];
    __shared__ unsigned int scan[RT];
    __shared__ unsigned int s_digit, s_r;
    __shared__ float s_sum[RT / 32];
    __shared__ float s_dinv;

    int row = blockIdx.x;  // global row 0..B*N-1
    int b = row >> 11;
    int tid = threadIdx.x;
    int lane = tid & 31;
    int warp = tid >> 5;
    float minb = funmap(g_minbits[b]);
    float mk = mask[row];
    float* rp = out + (size_t)row * NN;

#pragma unroll
    for (int q = 0; q < EPT; q++) {
        int j = tid + q * RT;
        float v = (rp[j] - minb) * mk;
        vals[j] = v;
        keys[j] = fmap(v);
    }
    __syncthreads();

    // radix select the KTOP-th largest key
    unsigned int prefix = 0;
    unsigned int r = KTOP;
    for (int shift = 24; shift >= 0; shift -= 8) {
        hist[tid] = 0;
        __syncthreads();
        unsigned int pmask = (shift == 24) ? 0u : (0xFFFFFFFFu << (shift + 8));
        int base = tid * EPT;
#pragma unroll
        for (int q = 0; q < EPT; q++) {
            unsigned int k = keys[base + q];
            bool match = ((k & pmask) == prefix);
            unsigned int d = match ? ((k >> shift) & 0xFFu) : 0xFFFFFFFFu;
            unsigned int peers = __match_any_sync(0xFFFFFFFFu, d);
            if (match && (lane == (__ffs(peers) - 1)))
                atomicAdd(&hist[d], __popc(peers));
        }
        __syncthreads();
        // parallel suffix-sum of hist -> scan
        scan[tid] = hist[tid];
        __syncthreads();
#pragma unroll
        for (int off = 1; off < 256; off <<= 1) {
            unsigned int t = (tid + off < 256) ? scan[tid + off] : 0u;
            __syncthreads();
            scan[tid] += t;
            __syncthreads();
        }
        unsigned int snext = (tid == 255) ? 0u : scan[tid + 1];
        if (scan[tid] >= r && snext < r) {
            s_digit = (unsigned int)tid;
            s_r = r - snext;
        }
        __syncthreads();
        prefix |= (s_digit << shift);
        r = s_r;
        __syncthreads();
    }
    unsigned int T = prefix;
    unsigned int eq_needed = r;

    // stable (lowest-index-first) resolution among keys == T
    int base = tid * EPT;
    unsigned int cnt = 0;
#pragma unroll
    for (int q = 0; q < EPT; q++) cnt += (keys[base + q] == T) ? 1u : 0u;
    scan[tid] = cnt;
    __syncthreads();
#pragma unroll
    for (int off = 1; off < RT; off <<= 1) {
        unsigned int t = (tid >= off) ? scan[tid - off] : 0u;
        __syncthreads();
        scan[tid] += t;
        __syncthreads();
    }
    unsigned int rank = scan[tid] - cnt;  // exclusive prefix

    float lsum = 0.f;
#pragma unroll
    for (int q = 0; q < EPT; q++) {
        int j = base + q;
        unsigned int k = keys[j];
        bool keep = (k > T) || (k == T && rank < eq_needed);
        if (k == T) rank++;
        float v = keep ? vals[j] : 0.0f;
        vals[j] = v;
        lsum += v;
    }
#pragma unroll
    for (int off = 16; off > 0; off >>= 1) lsum += __shfl_xor_sync(0xFFFFFFFFu, lsum, off);
    if (lane == 0) s_sum[warp] = lsum;
    __syncthreads();
    if (tid == 0) {
        float tot = 0.f;
#pragma unroll
        for (int w = 0; w < RT / 32; w++) tot += s_sum[w];
        float d = (tot > 0.f) ? (1.0f / sqrtf(tot)) : 0.0f;
        g_dinv[row] = d;
        s_dinv = d;
    }
    __syncthreads();
    float dinv = s_dinv;
#pragma unroll
    for (int q = 0; q < EPT; q++) {
        int j = tid + q * RT;
        rp[j] = vals[j] * dinv;  // d_i * A ; d_j applied in k_scale
    }
}

// out[b,i,j] *= d[b,j]
__global__ __launch_bounds__(256) void k_scale(float* __restrict__ out) {
    size_t idx4 = (size_t)blockIdx.x * blockDim.x + threadIdx.x;  // 16777216 float4s
    float4 v = ((float4*)out)[idx4];
    size_t col4 = idx4 & (NN / 4 - 1);
    size_t rowg = idx4 >> 9;
    size_t b = rowg >> 11;
    float4 dj = ((const float4*)g_dinv)[(b << 9) + col4];
    v.x *= dj.x;
    v.y *= dj.y;
    v.z *= dj.z;
    v.w *= dj.w;
    ((float4*)out)[idx4] = v;
}

extern "C" void kernel_launch(void* const* d_in, const int* in_sizes, int n_in,
                              void* d_out, int out_size) {
    const float* ge = (const float*)d_in[0];
    const float* mask = (const float*)d_in[1];
    const float* hs = (const float*)d_in[2];
    const float* W1 = (const float*)d_in[3];
    const float* b1 = (const float*)d_in[4];
    const float* W2 = (const float*)d_in[5];
    const float* b2 = (const float*)d_in[6];
    float* out = (float*)d_out;

    k_init<<<1, 32>>>();
    k_hb<<<BB, 512>>>(hs, W1, W2);
    k_gemm1<<<dim3(1024 / BN, (BB * NN) / BM), 256>>>(ge, mask, W1, b1, W2, b2);
    k_gemm2<<<dim3(NN / BN, NN / BM, BB), 256>>>(out);
    k_row<<<BB * NN, RT>>>(out, mask);
    k_scale<<<65536, 256>>>(out);
}